// round 6
// baseline (speedup 1.0000x reference)
#include <cuda_runtime.h>

#define N_BINS 85
#define NBLOCKS 1184            // 8 CTAs/SM * 148 SMs (empirical best shape)
#define GROUPS_PER_BLOCK 3
#define ACTIVE_THREADS (GROUPS_PER_BLOCK * N_BINS)   // 255
#define BLOCK_THREADS 256
#define TOTAL_GROUPS (NBLOCKS * GROUPS_PER_BLOCK)    // 3552

// Per-block column partials, TRANSPOSED: g_part[c * NBLOCKS + b].
// Columns contiguous -> stage 2 reads coalesced. Plain stores, overwritten
// every launch (deterministic, no reset needed). No dynamic allocation.
__device__ float g_part[N_BINS * NBLOCKS];

// ---------------------------------------------------------------------------
// Stage 1: grid-stride column reduction over "super-rows" (4 rows = 85 float4s).
// Thread t: group g = bx*3 + t/85, float4 position p = t%85.
// Its float4 covers fixed columns (4p+k) mod 85 for k=0..3.
// Epilogue is plain STG only — no fences/atomics polluting the stream tail.
// ---------------------------------------------------------------------------
__global__ void __launch_bounds__(BLOCK_THREADS, 8)
emd_stage1(const float4* __restrict__ in4, const float4* __restrict__ tg4,
           const float* __restrict__ in, const float* __restrict__ tg,
           int nsuper, int total_elems)
{
    __shared__ float sd[N_BINS];
    int t = threadIdx.x;
    if (t < N_BINS) sd[t] = 0.0f;

    float a0 = 0.f, a1 = 0.f, a2 = 0.f, a3 = 0.f;
    int p = 0;
    if (t < ACTIVE_THREADS) {
        int g = blockIdx.x * GROUPS_PER_BLOCK + (t / N_BINS);
        p = t % N_BINS;
        #pragma unroll 4
        for (int s = g; s < nsuper; s += TOTAL_GROUPS) {
            int idx = s * N_BINS + p;          // float4 index; ~10.6M max, fits int
            float4 a = in4[idx];
            float4 b = tg4[idx];
            a0 += a.x - b.x;
            a1 += a.y - b.y;
            a2 += a.z - b.z;
            a3 += a.w - b.w;
        }
    }
    __syncthreads();
    if (t < ACTIVE_THREADS) {
        atomicAdd(&sd[(4 * p) % N_BINS],     a0);
        atomicAdd(&sd[(4 * p + 1) % N_BINS], a1);
        atomicAdd(&sd[(4 * p + 2) % N_BINS], a2);
        atomicAdd(&sd[(4 * p + 3) % N_BINS], a3);
    }
    // Tail rows (B % 4 != 0): scalar, block 0 only. (B=500000 -> empty loop.)
    if (blockIdx.x == 0) {
        int tail_start = nsuper * (4 * N_BINS);
        for (int i = tail_start + t; i < total_elems; i += BLOCK_THREADS) {
            atomicAdd(&sd[i % N_BINS], in[i] - tg[i]);
        }
    }
    __syncthreads();
    if (t < N_BINS) g_part[t * NBLOCKS + blockIdx.x] = sd[t];   // transposed
}

// ---------------------------------------------------------------------------
// Stage 2: 1 block, 1024 threads. Warp w reduces columns w, w+32, ... over
// 1184 contiguous floats (coalesced, L2-resident), shuffle-reduce, abs,
// then thread 0 does the 85-step cumsum / weighted sum.
// ---------------------------------------------------------------------------
__global__ void emd_stage2(float* __restrict__ out)
{
    __shared__ float d[N_BINS];
    int w = threadIdx.x >> 5;
    int lane = threadIdx.x & 31;

    for (int c = w; c < N_BINS; c += 32) {
        const float* col = &g_part[c * NBLOCKS];
        float acc = 0.f;
        #pragma unroll 4
        for (int i = lane; i < NBLOCKS; i += 32) acc += col[i];
        #pragma unroll
        for (int o = 16; o > 0; o >>= 1)
            acc += __shfl_xor_sync(0xFFFFFFFFu, acc, o);
        if (lane == 0) d[c] = fabsf(acc);
    }
    __syncthreads();
    if (threadIdx.x == 0) {
        float cum = 0.f, loss = 0.f;
        #pragma unroll
        for (int j = 0; j < N_BINS; j++) {
            cum += d[j];
            loss += cum / (float)(j + 1);
        }
        out[0] = loss * 0.1f;
    }
}

extern "C" void kernel_launch(void* const* d_in, const int* in_sizes, int n_in,
                              void* d_out, int out_size)
{
    const float* in = (const float*)d_in[0];
    const float* tg = (const float*)d_in[1];
    int total = in_sizes[0];            // 500000 * 85
    int B = total / N_BINS;
    int nsuper = B / 4;

    emd_stage1<<<NBLOCKS, BLOCK_THREADS>>>((const float4*)in, (const float4*)tg,
                                           in, tg, nsuper, total);
    emd_stage2<<<1, 1024>>>((float*)d_out);
}

// round 7
// speedup vs baseline: 1.1667x; 1.1667x over previous
#include <cuda_runtime.h>

#define N_BINS 85
#define NBLOCKS 1184            // 8 CTAs/SM * 148 SMs (empirical best shape)
#define GROUPS_PER_BLOCK 3
#define ACTIVE_THREADS (GROUPS_PER_BLOCK * N_BINS)   // 255
#define BLOCK_THREADS 256
#define TOTAL_GROUPS (NBLOCKS * GROUPS_PER_BLOCK)    // 3552

// Globals (zero at module load; last block resets them via atomicExch each
// call, so graph replays are deterministic). No dynamic allocation.
__device__ float g_acc[N_BINS];
__device__ unsigned int g_count;

// ---------------------------------------------------------------------------
// Single fused kernel. Mainloop identical to the 46us stage-1 (92% of HBM).
// Cheap last-block epilogue (threadFenceReduction pattern):
//   publishers: plain atomicAdd into g_acc (L2-coherent)
//   __syncthreads()  -> publishers' atomics visible to t0
//   t0: ONE cumulative __threadfence() + ticket atomic  (release)
//   last block: t0 fence (acquire), readers atomicExch(g_acc, 0) = read+reset
// ---------------------------------------------------------------------------
__global__ void __launch_bounds__(BLOCK_THREADS, 8)
emd_fused(const float4* __restrict__ in4, const float4* __restrict__ tg4,
          const float* __restrict__ in, const float* __restrict__ tg,
          int nsuper, int total_elems, float* __restrict__ out)
{
    __shared__ float sd[N_BINS];
    __shared__ int islast;
    int t = threadIdx.x;
    if (t < N_BINS) sd[t] = 0.0f;

    float a0 = 0.f, a1 = 0.f, a2 = 0.f, a3 = 0.f;
    int p = 0;
    if (t < ACTIVE_THREADS) {
        int g = blockIdx.x * GROUPS_PER_BLOCK + (t / N_BINS);
        p = t % N_BINS;
        #pragma unroll 4
        for (int s = g; s < nsuper; s += TOTAL_GROUPS) {
            int idx = s * N_BINS + p;          // float4 index; ~10.6M max, fits int
            float4 a = in4[idx];
            float4 b = tg4[idx];
            a0 += a.x - b.x;
            a1 += a.y - b.y;
            a2 += a.z - b.z;
            a3 += a.w - b.w;
        }
    }
    __syncthreads();
    if (t < ACTIVE_THREADS) {
        atomicAdd(&sd[(4 * p) % N_BINS],     a0);
        atomicAdd(&sd[(4 * p + 1) % N_BINS], a1);
        atomicAdd(&sd[(4 * p + 2) % N_BINS], a2);
        atomicAdd(&sd[(4 * p + 3) % N_BINS], a3);
    }
    // Tail rows (B % 4 != 0): scalar, block 0 only. (B=500000 -> empty loop.)
    if (blockIdx.x == 0) {
        int tail_start = nsuper * (4 * N_BINS);
        for (int i = tail_start + t; i < total_elems; i += BLOCK_THREADS) {
            atomicAdd(&sd[i % N_BINS], in[i] - tg[i]);
        }
    }
    __syncthreads();

    // Publish block partials via L2 float atomics (85 distinct addresses).
    if (t < N_BINS) atomicAdd(&g_acc[t], sd[t]);
    __syncthreads();          // publishers' atomics visible to t0 (block scope)
    if (t == 0) {
        __threadfence();      // ONE cumulative release fence per block
        unsigned int ticket = atomicAdd(&g_count, 1u);
        islast = (ticket == NBLOCKS - 1u);
    }
    __syncthreads();

    if (islast) {
        __shared__ float d[N_BINS];
        if (t == 0) __threadfence();           // acquire side
        __syncthreads();
        if (t < N_BINS) {
            // L2-coherent read + reset in one atomic; no L1 staleness possible.
            float v = atomicExch(&g_acc[t], 0.0f);
            d[t] = fabsf(v);
        }
        __syncthreads();
        if (t == 0) {
            float cum = 0.f, loss = 0.f;
            #pragma unroll
            for (int j = 0; j < N_BINS; j++) {
                cum += d[j];
                loss += cum / (float)(j + 1);
            }
            out[0] = loss * 0.1f;
            atomicExch(&g_count, 0u);          // reset ticket for next replay
        }
    }
}

extern "C" void kernel_launch(void* const* d_in, const int* in_sizes, int n_in,
                              void* d_out, int out_size)
{
    const float* in = (const float*)d_in[0];
    const float* tg = (const float*)d_in[1];
    int total = in_sizes[0];            // 500000 * 85
    int B = total / N_BINS;
    int nsuper = B / 4;

    emd_fused<<<NBLOCKS, BLOCK_THREADS>>>((const float4*)in, (const float4*)tg,
                                          in, tg, nsuper, total, (float*)d_out);
}